// round 14
// baseline (speedup 1.0000x reference)
#include <cuda_runtime.h>
#include <cuda_fp16.h>
#include <cstdint>

#define B_ 32
#define D_ 256
#define T_ 2048
#define K_ 1024
#define N_ (B_ * T_)            // 65536 vectors
#define QSIZE (B_ * D_ * T_)    // 16777216 quantized elements

// ---------------- device scratch (no allocation allowed) -------------------
__device__ float  g_e2[K_];
__device__ float  g_x2[N_];
__device__ int    g_idx[N_];
__device__ double g_loss;
// Pre-split codebook (scaled by 2^14): e*2^14 = h + l (residual <= 2^-24 rel)
__device__ __align__(16) __half g_eh[K_ * D_];
__device__ __align__(16) __half g_el[K_ * D_];

#define SCALE_X 16.0f            // 2^4
#define SCALE_E 16384.0f         // 2^14
#define UNSCALE_M2 (-7.62939453125e-6f)   // -2 * 2^-18, exact power of two

// ---------------- smem layout (dynamic) -------------------------------------
// A: [split 0..1][kc 0..3] 16KB tiles of [128 tok][64 d fp16, swizzled rows]
#define SMA   0                 // 131072 bytes
// B double buffer: 2 x 32KB; each: [split 0..1][kc 0..3][32 code][64 d fp16]
#define SMB0  131072
#define SME2  196608            // 1024 floats (full e2 table)
#define SMRV  200704            // 128*2 floats
#define SMRI  201728            // 128*2 ints
#define SMLOSS 202752           // 128 doubles
#define SMTOT 203776

__device__ __forceinline__ uint32_t smem_u32(const void* p) {
    uint32_t a;
    asm("{ .reg .u64 t; cvta.to.shared.u64 t, %1; cvt.u32.u64 %0, t; }"
        : "=r"(a) : "l"(p));
    return a;
}
__device__ __forceinline__ void ldsm_x4(uint32_t addr, uint32_t* r) {
    asm volatile(
        "ldmatrix.sync.aligned.m8n8.x4.shared.b16 {%0,%1,%2,%3}, [%4];"
        : "=r"(r[0]), "=r"(r[1]), "=r"(r[2]), "=r"(r[3]) : "r"(addr));
}
__device__ __forceinline__ void mma16816(float* c, const uint32_t* a,
                                         const uint32_t* b) {
    asm volatile(
        "mma.sync.aligned.m16n8k16.row.col.f32.f16.f16.f32 "
        "{%0,%1,%2,%3}, {%4,%5,%6,%7}, {%8,%9}, {%0,%1,%2,%3};"
        : "+f"(c[0]), "+f"(c[1]), "+f"(c[2]), "+f"(c[3])
        : "r"(a[0]), "r"(a[1]), "r"(a[2]), "r"(a[3]), "r"(b[0]), "r"(b[1]));
}
__device__ __forceinline__ void cp16(uint32_t dst, const void* src) {
    asm volatile("cp.async.cg.shared.global [%0], [%1], 16;"
                 :: "r"(dst), "l"(src));
}

// ---------------------------------------------------------------------------
// Kernel 1 (fused prep): blocks [0, K_) do codebook prep (e2 + fp16 split,
// zero loss); blocks [K_, K_+256) compute x2[n] per vector.
// ---------------------------------------------------------------------------
__global__ void prep_kernel(const float* __restrict__ E,
                            const float* __restrict__ X) {
    __shared__ double s[256];
    int bx = blockIdx.x;
    if (bx < K_) {
        int k = bx;
        int d = threadIdx.x;
        size_t o = (size_t)k * D_ + d;
        float v = E[o];

        float es = __fmul_rn(v, SCALE_E);       // exact power-of-2 scale
        __half h = __float2half_rn(es);
        __half l = __float2half_rn(__fsub_rn(es, __half2float(h)));
        g_eh[o] = h;
        g_el[o] = l;

        float sq = __fmul_rn(v, v);
        s[d] = (double)sq;
        __syncthreads();
        for (int off = 128; off > 0; off >>= 1) {
            if (d < off) s[d] += s[d + off];
            __syncthreads();
        }
        if (d == 0) g_e2[k] = (float)s[0];
        if (k == 0 && d == 0) g_loss = 0.0;
    } else {
        int id = bx - K_;                       // 0..255
        int b  = id >> 3;
        int t  = (id & 7) * 256 + threadIdx.x;
        const float* xp = X + (size_t)b * (D_ * T_) + t;
        double acc = 0.0;
#pragma unroll 8
        for (int d = 0; d < D_; d++) {
            float x = xp[(size_t)d * T_];
            acc += (double)__fmul_rn(x, x);
        }
        g_x2[b * T_ + t] = (float)acc;
    }
}

// ---------------------------------------------------------------------------
// Kernel 2: HMMA distance GEMM + argmin (R9 config — proven fastest) with
// fused loss: per-CTA sum of winning distances -> atomicAdd(g_loss).
// CTA = 128 tokens, 8 warps: wm = wid&3 (32-token group), wn = wid>>2
// (16-code half of the 32-code tile). 32 code-tiles, double-buffered via
// cp.async. dot = (AhBh + AhBl + AlBh), fp16 splits of scaled x,e; fp32 acc.
// Epilogue: dist = fl(fl(x2+e2) - 2*fl(dot)); strict <, tie -> smaller k.
// ---------------------------------------------------------------------------
__global__ __launch_bounds__(256, 1)
void argmin_mma_kernel(const float* __restrict__ X) {
    extern __shared__ char smem[];
    const uint32_t sb = smem_u32(smem);
    const int tid  = threadIdx.x;
    const int lane = tid & 31, wid = tid >> 5;
    const int wm = wid & 3, wn = wid >> 2;
    const int bx = blockIdx.x;
    const int b  = bx >> 4, t0 = (bx & 15) * 128;
    const int n0 = b * T_ + t0;
    const float* Xb = X + (size_t)b * (D_ * T_) + t0;

    // ---- stage A: X tile -> fp16 h/l (scaled by 2^4), swizzled [tok][d] ---
#pragma unroll 4
    for (int i = 0; i < 16; i++) {
        int idx = tid + i * 256;          // 0..4095
        int kc  = idx >> 10;              // 0..3
        int rem = idx & 1023;
        int dp  = rem >> 5;               // d-pair 0..31
        int c4  = rem & 31;               // float4 over tok
        int dg  = kc * 64 + dp * 2;
        float4 va = *(const float4*)(Xb + (size_t)dg * T_ + c4 * 4);
        float4 vb = *(const float4*)(Xb + (size_t)(dg + 1) * T_ + c4 * 4);
        float fa[4] = {va.x, va.y, va.z, va.w};
        float fb[4] = {vb.x, vb.y, vb.z, vb.w};
#pragma unroll
        for (int u = 0; u < 4; u++) {
            int tok = c4 * 4 + u;
            float x0 = __fmul_rn(fa[u], SCALE_X);
            float x1 = __fmul_rn(fb[u], SCALE_X);
            __half h0 = __float2half_rn(x0);
            __half l0 = __float2half_rn(__fsub_rn(x0, __half2float(h0)));
            __half h1 = __float2half_rn(x1);
            __half l1 = __float2half_rn(__fsub_rn(x1, __half2float(h1)));
            uint32_t off = (uint32_t)(tok * 128 + ((dp * 4) ^ ((tok & 7) << 4)));
            *(uint32_t*)(smem + SMA + kc * 16384 + off) =
                (uint32_t)__half_as_ushort(h0) |
                ((uint32_t)__half_as_ushort(h1) << 16);
            *(uint32_t*)(smem + SMA + 65536 + kc * 16384 + off) =
                (uint32_t)__half_as_ushort(l0) |
                ((uint32_t)__half_as_ushort(l1) << 16);
        }
    }
    // stage full e2 table (read only after later barriers)
    {
        float* se2w = (float*)(smem + SME2);
#pragma unroll
        for (int i = 0; i < 4; i++) se2w[tid + i * 256] = g_e2[tid + i * 256];
    }

    // per-thread owned token rows (4 slots: mb*2 + rowhalf)
    float x2own[4];
#pragma unroll
    for (int slot = 0; slot < 4; slot++) {
        int trow = wm * 32 + (slot >> 1) * 16 + (slot & 1) * 8 + (lane >> 2);
        x2own[slot] = g_x2[n0 + trow];
    }

    float best[4];
    int   bidx[4];
#pragma unroll
    for (int s = 0; s < 4; s++) { best[s] = 3.4e38f; bidx[s] = 0; }

    // lane constants for ldmatrix addressing
    const int g = lane >> 3, r = lane & 7;
    const int tok0  = wm * 32 + (g & 1) * 8 + r;   // A row (mb adds 16)
    const int khA   = g >> 1;
    const uint32_t xrA = (uint32_t)((tok0 & 7) << 4);
    const int code0 = (g >> 1) * 8 + r;            // B row within 16-block
    const int khB   = g & 1;
    const uint32_t xrB = (uint32_t)((code0 & 7) << 4);
    const uint32_t bcol = (uint32_t)((wn * 16 + code0) * 128);

    // ---- B-tile prefetch (32 codes = 32KB: 2 splits x 4 kc x 32 rows) -----
    auto prefetch = [&](int ct) {
        int cbase = ct * 32;
        uint32_t bufo = sb + SMB0 + (uint32_t)(ct & 1) * 32768;
#pragma unroll
        for (int i = 0; i < 8; i++) {
            int idx = tid + i * 256;       // 0..2047
            int s   = idx >> 10;
            int rem = idx & 1023;
            int kc  = rem >> 8;
            int r2  = rem & 255;
            int row = r2 >> 3, c16 = r2 & 7;
            const __half* src = (s ? g_el : g_eh)
                + (size_t)(cbase + row) * D_ + kc * 64 + c16 * 8;
            uint32_t dst = bufo + s * 16384 + kc * 4096 + row * 128
                         + (uint32_t)((c16 * 16) ^ ((row & 7) << 4));
            cp16(dst, src);
        }
        asm volatile("cp.async.commit_group;" ::: "memory");
    };

    prefetch(0);

    const float* se2 = (const float*)(smem + SME2);

    for (int ct = 0; ct < 32; ct++) {
        __syncthreads();                       // all done reading buf (ct+1)&1
        if (ct + 1 < 32) {
            prefetch(ct + 1);
            asm volatile("cp.async.wait_group 1;" ::: "memory");
        } else {
            asm volatile("cp.async.wait_group 0;" ::: "memory");
        }
        __syncthreads();                       // tile ct visible block-wide

        // ---- mainloop: 32 codes x K=256 (16 k16 steps) -------------------
        float acc[2][2][4];
#pragma unroll
        for (int mb = 0; mb < 2; mb++)
#pragma unroll
            for (int nb = 0; nb < 2; nb++)
#pragma unroll
                for (int e = 0; e < 4; e++) acc[mb][nb][e] = 0.f;

        uint32_t bufo = sb + SMB0 + (uint32_t)(ct & 1) * 32768;
#pragma unroll
        for (int kc = 0; kc < 4; kc++) {
            uint32_t abase = sb + SMA + kc * 16384 + tok0 * 128;
            uint32_t bbase = bufo + kc * 4096 + bcol;
#pragma unroll
            for (int ks = 0; ks < 4; ks++) {
                uint32_t da = (uint32_t)((ks * 32 + khA * 16) ^ xrA);
                uint32_t db = (uint32_t)((ks * 32 + khB * 16) ^ xrB);
                uint32_t Ah[2][4], Al[2][4], Bh[4], Bl[4];
#pragma unroll
                for (int mb = 0; mb < 2; mb++) {
                    ldsm_x4(abase + mb * 2048 + da, Ah[mb]);
                    ldsm_x4(abase + 65536 + mb * 2048 + da, Al[mb]);
                }
                ldsm_x4(bbase + db, Bh);
                ldsm_x4(bbase + 16384 + db, Bl);
#pragma unroll
                for (int mb = 0; mb < 2; mb++)
#pragma unroll
                    for (int nb = 0; nb < 2; nb++) {
                        const uint32_t* bh = &Bh[2 * nb];
                        const uint32_t* bl = &Bl[2 * nb];
                        mma16816(acc[mb][nb], Ah[mb], bh);
                        mma16816(acc[mb][nb], Ah[mb], bl);
                        mma16816(acc[mb][nb], Al[mb], bh);
                    }
            }
        }

        // ---- epilogue: exact ref rounding + running argmin ---------------
        int cbase = ct * 32;
#pragma unroll
        for (int mb = 0; mb < 2; mb++)
#pragma unroll
            for (int nb = 0; nb < 2; nb++)
#pragma unroll
                for (int e = 0; e < 4; e++) {
                    int slot = mb * 2 + (e >> 1);
                    int k    = cbase + wn * 16 + nb * 8
                             + 2 * (lane & 3) + (e & 1);
                    float C    = __fadd_rn(x2own[slot], se2[k]);
                    float m2g  = __fmul_rn(acc[mb][nb][e], UNSCALE_M2); // exact
                    float dist = __fadd_rn(C, m2g);
                    if (dist < best[slot]) { best[slot] = dist; bidx[slot] = k; }
                }
    }

    // ---- reduce: 4 lanes per row (shfl), then 2 wn warps (smem) ----------
    float* rv = (float*)(smem + SMRV);
    int*   ri = (int*)(smem + SMRI);
    __syncthreads();
#pragma unroll
    for (int slot = 0; slot < 4; slot++) {
        float v = best[slot];
        int   ix = bidx[slot];
#pragma unroll
        for (int off = 1; off < 4; off <<= 1) {
            float ov = __shfl_xor_sync(0xffffffffu, v, off);
            int   oi = __shfl_xor_sync(0xffffffffu, ix, off);
            if (ov < v || (ov == v && oi < ix)) { v = ov; ix = oi; }
        }
        if ((lane & 3) == 0) {
            int trow = wm * 32 + (slot >> 1) * 16 + (slot & 1) * 8 + (lane >> 2);
            rv[trow * 2 + wn] = v;
            ri[trow * 2 + wn] = ix;
        }
    }
    __syncthreads();
    double* sl = (double*)(smem + SMLOSS);
    if (tid < 128) {
        float v0 = rv[tid * 2], v1 = rv[tid * 2 + 1];
        int   i0 = ri[tid * 2], i1 = ri[tid * 2 + 1];
        bool second = (v1 < v0 || (v1 == v0 && i1 < i0));
        g_idx[n0 + tid] = second ? i1 : i0;
        sl[tid] = (double)(second ? v1 : v0);   // winning distance = ||x-q||^2
    }
    __syncthreads();
    // reduce 128 doubles -> atomicAdd into g_loss
    for (int off = 64; off > 0; off >>= 1) {
        if (tid < off) sl[tid] += sl[tid + off];
        __syncthreads();
    }
    if (tid == 0) atomicAdd(&g_loss, sl[0]);
}

// ---------------------------------------------------------------------------
// Kernel 3: pure codebook scatter -> quantized output (no X read, no loss).
// E rows (1MB total) are L2-resident; writes fully coalesced over t.
// ---------------------------------------------------------------------------
__global__ __launch_bounds__(256) void gather_kernel(
    const float* __restrict__ E, float* __restrict__ out)
{
    __shared__ float sq[256][33];
    __shared__ int   sidx[256];

    const int b   = blockIdx.y;
    const int t0  = blockIdx.x * 256;
    const int tid = threadIdx.x;
    const int t   = t0 + tid;

    sidx[tid] = g_idx[b * T_ + t];
    __syncthreads();

    const int rg = tid >> 3;
    const int rl = tid & 7;

    for (int d0 = 0; d0 < D_; d0 += 32) {
#pragma unroll
        for (int r0 = 0; r0 < 256; r0 += 32) {
            int row = r0 + rg;
            float4 v = *reinterpret_cast<const float4*>(
                E + (size_t)sidx[row] * D_ + d0 + rl * 4);
            sq[row][rl * 4 + 0] = v.x;
            sq[row][rl * 4 + 1] = v.y;
            sq[row][rl * 4 + 2] = v.z;
            sq[row][rl * 4 + 3] = v.w;
        }
        __syncthreads();
#pragma unroll
        for (int dd = 0; dd < 32; dd++) {
            int d = d0 + dd;
            out[((size_t)b * D_ + d) * T_ + t] = sq[tid][dd];
        }
        __syncthreads();
    }
}

// ---------------------------------------------------------------------------
// Kernel 4: loss scalar + indices-as-float.
// loss = q_latent + 0.25 * e_latent = 1.25 * mean(||x - q||^2 per element)
// ---------------------------------------------------------------------------
__global__ void finalize_kernel(float* __restrict__ out, int out_size) {
    int i = blockIdx.x * blockDim.x + threadIdx.x;
    if (i == 0 && out_size > QSIZE) {
        out[QSIZE] = (float)(g_loss * 1.25 / (double)QSIZE);
    }
    if (i < N_ && out_size >= QSIZE + 1 + N_) {
        out[QSIZE + 1 + i] = (float)g_idx[i];
    }
}

// ---------------------------------------------------------------------------
extern "C" void kernel_launch(void* const* d_in, const int* in_sizes, int n_in,
                              void* d_out, int out_size) {
    const float* X = (const float*)d_in[0];   // [B, D, T] f32
    const float* E = (const float*)d_in[1];   // [K, D]   f32
    float* out = (float*)d_out;

    cudaFuncSetAttribute(argmin_mma_kernel,
                         cudaFuncAttributeMaxDynamicSharedMemorySize, SMTOT);

    prep_kernel<<<K_ + 256, 256>>>(E, X);
    argmin_mma_kernel<<<N_ / 128, 256, SMTOT>>>(X);
    gather_kernel<<<dim3(T_ / 256, B_), 256>>>(E, out);
    finalize_kernel<<<(N_ + 255) / 256, 256>>>(out, out_size);
}

// round 15
// speedup vs baseline: 1.0444x; 1.0444x over previous
#include <cuda_runtime.h>
#include <cuda_fp16.h>
#include <cstdint>

#define B_ 32
#define D_ 256
#define T_ 2048
#define K_ 1024
#define N_ (B_ * T_)            // 65536 vectors
#define QSIZE (B_ * D_ * T_)    // 16777216 quantized elements

// ---------------- device scratch (no allocation allowed) -------------------
__device__ float  g_e2[K_];
__device__ float  g_x2[N_];
__device__ double g_loss;
// Pre-split codebook (scaled by 2^14): e*2^14 = h + l (residual <= 2^-24 rel)
__device__ __align__(16) __half g_eh[K_ * D_];
__device__ __align__(16) __half g_el[K_ * D_];

#define SCALE_X 16.0f            // 2^4
#define SCALE_E 16384.0f         // 2^14
#define UNSCALE_M2 (-7.62939453125e-6f)   // -2 * 2^-18, exact power of two

// ---------------- smem layout (dynamic) -------------------------------------
// A: [split 0..1][kc 0..3] 16KB tiles of [128 tok][64 d fp16, swizzled rows]
// (reused after the mainloop as the output staging buffer: 128 x 65 floats)
#define SMA   0                 // 131072 bytes
// B double buffer: 2 x 32KB; each: [split 0..1][kc 0..3][32 code][64 d fp16]
#define SMB0  131072
#define SME2  196608            // 1024 floats (full e2 table)
#define SMRV  200704            // 128*2 floats
#define SMRI  201728            // 128*2 ints
#define SMIDX 202752            // 128 ints (final per-token index)
#define SMLOSS 203264           // 128 doubles
#define SMTOT 204288

__device__ __forceinline__ uint32_t smem_u32(const void* p) {
    uint32_t a;
    asm("{ .reg .u64 t; cvta.to.shared.u64 t, %1; cvt.u32.u64 %0, t; }"
        : "=r"(a) : "l"(p));
    return a;
}
__device__ __forceinline__ void ldsm_x4(uint32_t addr, uint32_t* r) {
    asm volatile(
        "ldmatrix.sync.aligned.m8n8.x4.shared.b16 {%0,%1,%2,%3}, [%4];"
        : "=r"(r[0]), "=r"(r[1]), "=r"(r[2]), "=r"(r[3]) : "r"(addr));
}
__device__ __forceinline__ void mma16816(float* c, const uint32_t* a,
                                         const uint32_t* b) {
    asm volatile(
        "mma.sync.aligned.m16n8k16.row.col.f32.f16.f16.f32 "
        "{%0,%1,%2,%3}, {%4,%5,%6,%7}, {%8,%9}, {%0,%1,%2,%3};"
        : "+f"(c[0]), "+f"(c[1]), "+f"(c[2]), "+f"(c[3])
        : "r"(a[0]), "r"(a[1]), "r"(a[2]), "r"(a[3]), "r"(b[0]), "r"(b[1]));
}
__device__ __forceinline__ void cp16(uint32_t dst, const void* src) {
    asm volatile("cp.async.cg.shared.global [%0], [%1], 16;"
                 :: "r"(dst), "l"(src));
}

// ---------------------------------------------------------------------------
// Kernel 1: e2[k] = fl32(sum fl32(E^2)); zero loss accumulator.
// ---------------------------------------------------------------------------
__global__ void e2_kernel(const float* __restrict__ E) {
    int k = blockIdx.x;
    int d = threadIdx.x;
    float v = E[(size_t)k * D_ + d];
    float sq = __fmul_rn(v, v);
    __shared__ double s[256];
    s[d] = (double)sq;
    __syncthreads();
    for (int off = 128; off > 0; off >>= 1) {
        if (d < off) s[d] += s[d + off];
        __syncthreads();
    }
    if (d == 0) g_e2[k] = (float)s[0];
    if (k == 0 && d == 0) g_loss = 0.0;
}

// ---------------------------------------------------------------------------
// Kernel 1b: pre-split codebook into fp16 hi/lo of e*2^14.
// ---------------------------------------------------------------------------
__global__ void splitE_kernel(const float* __restrict__ E) {
    int k = blockIdx.x;
    int d = threadIdx.x;
    size_t o = (size_t)k * D_ + d;
    float es = __fmul_rn(E[o], SCALE_E);        // exact power-of-2 scale
    __half h = __float2half_rn(es);
    __half l = __float2half_rn(__fsub_rn(es, __half2float(h)));
    g_eh[o] = h;
    g_el[o] = l;
}

// ---------------------------------------------------------------------------
// Kernel 1c: x2[n] per vector (double accumulation of fl32 squares).
// ---------------------------------------------------------------------------
__global__ __launch_bounds__(256) void x2_kernel(const float* __restrict__ X) {
    int b = blockIdx.y;
    int t = blockIdx.x * 256 + threadIdx.x;
    const float* xp = X + (size_t)b * (D_ * T_) + t;
    double acc = 0.0;
#pragma unroll 8
    for (int d = 0; d < D_; d++) {
        float x = xp[(size_t)d * T_];
        acc += (double)__fmul_rn(x, x);
    }
    g_x2[b * T_ + t] = (float)acc;
}

// ---------------------------------------------------------------------------
// Kernel 2: HMMA distance GEMM + argmin (R9 config — best measured), with
// fused tail: quantized output + indices written directly by the CTA, and
// loss = sum of winning distances -> atomicAdd(g_loss).
// CTA = 128 tokens, 8 warps: wm = wid&3 (32-token group), wn = wid>>2
// (16-code half of the 32-code tile). 32 code-tiles, double-buffered via
// cp.async. dot = (AhBh + AhBl + AlBh), fp16 splits of scaled x,e; fp32 acc.
// Epilogue: dist = fl(fl(x2+e2) - 2*fl(dot)); strict <, tie -> smaller k.
// ---------------------------------------------------------------------------
__global__ __launch_bounds__(256, 1)
void argmin_mma_kernel(const float* __restrict__ X,
                       const float* __restrict__ Eg,
                       float* __restrict__ out, int out_size) {
    extern __shared__ char smem[];
    const uint32_t sb = smem_u32(smem);
    const int tid  = threadIdx.x;
    const int lane = tid & 31, wid = tid >> 5;
    const int wm = wid & 3, wn = wid >> 2;
    const int bx = blockIdx.x;
    const int b  = bx >> 4, t0 = (bx & 15) * 128;
    const int n0 = b * T_ + t0;
    const float* Xb = X + (size_t)b * (D_ * T_) + t0;

    // ---- stage A: X tile -> fp16 h/l (scaled by 2^4), swizzled [tok][d] ---
#pragma unroll 4
    for (int i = 0; i < 16; i++) {
        int idx = tid + i * 256;          // 0..4095
        int kc  = idx >> 10;              // 0..3
        int rem = idx & 1023;
        int dp  = rem >> 5;               // d-pair 0..31
        int c4  = rem & 31;               // float4 over tok
        int dg  = kc * 64 + dp * 2;
        float4 va = *(const float4*)(Xb + (size_t)dg * T_ + c4 * 4);
        float4 vb = *(const float4*)(Xb + (size_t)(dg + 1) * T_ + c4 * 4);
        float fa[4] = {va.x, va.y, va.z, va.w};
        float fb[4] = {vb.x, vb.y, vb.z, vb.w};
#pragma unroll
        for (int u = 0; u < 4; u++) {
            int tok = c4 * 4 + u;
            float x0 = __fmul_rn(fa[u], SCALE_X);
            float x1 = __fmul_rn(fb[u], SCALE_X);
            __half h0 = __float2half_rn(x0);
            __half l0 = __float2half_rn(__fsub_rn(x0, __half2float(h0)));
            __half h1 = __float2half_rn(x1);
            __half l1 = __float2half_rn(__fsub_rn(x1, __half2float(h1)));
            uint32_t off = (uint32_t)(tok * 128 + ((dp * 4) ^ ((tok & 7) << 4)));
            *(uint32_t*)(smem + SMA + kc * 16384 + off) =
                (uint32_t)__half_as_ushort(h0) |
                ((uint32_t)__half_as_ushort(h1) << 16);
            *(uint32_t*)(smem + SMA + 65536 + kc * 16384 + off) =
                (uint32_t)__half_as_ushort(l0) |
                ((uint32_t)__half_as_ushort(l1) << 16);
        }
    }
    // stage full e2 table (read only after later barriers)
    {
        float* se2w = (float*)(smem + SME2);
#pragma unroll
        for (int i = 0; i < 4; i++) se2w[tid + i * 256] = g_e2[tid + i * 256];
    }

    // per-thread owned token rows (4 slots: mb*2 + rowhalf)
    float x2own[4];
#pragma unroll
    for (int slot = 0; slot < 4; slot++) {
        int trow = wm * 32 + (slot >> 1) * 16 + (slot & 1) * 8 + (lane >> 2);
        x2own[slot] = g_x2[n0 + trow];
    }

    float best[4];
    int   bidx[4];
#pragma unroll
    for (int s = 0; s < 4; s++) { best[s] = 3.4e38f; bidx[s] = 0; }

    // lane constants for ldmatrix addressing
    const int g = lane >> 3, r = lane & 7;
    const int tok0  = wm * 32 + (g & 1) * 8 + r;   // A row (mb adds 16)
    const int khA   = g >> 1;
    const uint32_t xrA = (uint32_t)((tok0 & 7) << 4);
    const int code0 = (g >> 1) * 8 + r;            // B row within 16-block
    const int khB   = g & 1;
    const uint32_t xrB = (uint32_t)((code0 & 7) << 4);
    const uint32_t bcol = (uint32_t)((wn * 16 + code0) * 128);

    // ---- B-tile prefetch (32 codes = 32KB: 2 splits x 4 kc x 32 rows) -----
    auto prefetch = [&](int ct) {
        int cbase = ct * 32;
        uint32_t bufo = sb + SMB0 + (uint32_t)(ct & 1) * 32768;
#pragma unroll
        for (int i = 0; i < 8; i++) {
            int idx = tid + i * 256;       // 0..2047
            int s   = idx >> 10;
            int rem = idx & 1023;
            int kc  = rem >> 8;
            int r2  = rem & 255;
            int row = r2 >> 3, c16 = r2 & 7;
            const __half* src = (s ? g_el : g_eh)
                + (size_t)(cbase + row) * D_ + kc * 64 + c16 * 8;
            uint32_t dst = bufo + s * 16384 + kc * 4096 + row * 128
                         + (uint32_t)((c16 * 16) ^ ((row & 7) << 4));
            cp16(dst, src);
        }
        asm volatile("cp.async.commit_group;" ::: "memory");
    };

    prefetch(0);

    const float* se2 = (const float*)(smem + SME2);

    for (int ct = 0; ct < 32; ct++) {
        __syncthreads();                       // all done reading buf (ct+1)&1
        if (ct + 1 < 32) {
            prefetch(ct + 1);
            asm volatile("cp.async.wait_group 1;" ::: "memory");
        } else {
            asm volatile("cp.async.wait_group 0;" ::: "memory");
        }
        __syncthreads();                       // tile ct visible block-wide

        // ---- mainloop: 32 codes x K=256 (16 k16 steps) -------------------
        float acc[2][2][4];
#pragma unroll
        for (int mb = 0; mb < 2; mb++)
#pragma unroll
            for (int nb = 0; nb < 2; nb++)
#pragma unroll
                for (int e = 0; e < 4; e++) acc[mb][nb][e] = 0.f;

        uint32_t bufo = sb + SMB0 + (uint32_t)(ct & 1) * 32768;
#pragma unroll
        for (int kc = 0; kc < 4; kc++) {
            uint32_t abase = sb + SMA + kc * 16384 + tok0 * 128;
            uint32_t bbase = bufo + kc * 4096 + bcol;
#pragma unroll
            for (int ks = 0; ks < 4; ks++) {
                uint32_t da = (uint32_t)((ks * 32 + khA * 16) ^ xrA);
                uint32_t db = (uint32_t)((ks * 32 + khB * 16) ^ xrB);
                uint32_t Ah[2][4], Al[2][4], Bh[4], Bl[4];
#pragma unroll
                for (int mb = 0; mb < 2; mb++) {
                    ldsm_x4(abase + mb * 2048 + da, Ah[mb]);
                    ldsm_x4(abase + 65536 + mb * 2048 + da, Al[mb]);
                }
                ldsm_x4(bbase + db, Bh);
                ldsm_x4(bbase + 16384 + db, Bl);
#pragma unroll
                for (int mb = 0; mb < 2; mb++)
#pragma unroll
                    for (int nb = 0; nb < 2; nb++) {
                        const uint32_t* bh = &Bh[2 * nb];
                        const uint32_t* bl = &Bl[2 * nb];
                        mma16816(acc[mb][nb], Ah[mb], bh);
                        mma16816(acc[mb][nb], Ah[mb], bl);
                        mma16816(acc[mb][nb], Al[mb], bh);
                    }
            }
        }

        // ---- epilogue: exact ref rounding + running argmin ---------------
        int cbase = ct * 32;
#pragma unroll
        for (int mb = 0; mb < 2; mb++)
#pragma unroll
            for (int nb = 0; nb < 2; nb++)
#pragma unroll
                for (int e = 0; e < 4; e++) {
                    int slot = mb * 2 + (e >> 1);
                    int k    = cbase + wn * 16 + nb * 8
                             + 2 * (lane & 3) + (e & 1);
                    float C    = __fadd_rn(x2own[slot], se2[k]);
                    float m2g  = __fmul_rn(acc[mb][nb][e], UNSCALE_M2); // exact
                    float dist = __fadd_rn(C, m2g);
                    if (dist < best[slot]) { best[slot] = dist; bidx[slot] = k; }
                }
    }

    // ---- reduce: 4 lanes per row (shfl), then 2 wn warps (smem) ----------
    float* rv = (float*)(smem + SMRV);
    int*   ri = (int*)(smem + SMRI);
    __syncthreads();
#pragma unroll
    for (int slot = 0; slot < 4; slot++) {
        float v = best[slot];
        int   ix = bidx[slot];
#pragma unroll
        for (int off = 1; off < 4; off <<= 1) {
            float ov = __shfl_xor_sync(0xffffffffu, v, off);
            int   oi = __shfl_xor_sync(0xffffffffu, ix, off);
            if (ov < v || (ov == v && oi < ix)) { v = ov; ix = oi; }
        }
        if ((lane & 3) == 0) {
            int trow = wm * 32 + (slot >> 1) * 16 + (slot & 1) * 8 + (lane >> 2);
            rv[trow * 2 + wn] = v;
            ri[trow * 2 + wn] = ix;
        }
    }
    __syncthreads();
    int*    si = (int*)(smem + SMIDX);
    double* sl = (double*)(smem + SMLOSS);
    if (tid < 128) {
        float v0 = rv[tid * 2], v1 = rv[tid * 2 + 1];
        int   i0 = ri[tid * 2], i1 = ri[tid * 2 + 1];
        bool second = (v1 < v0 || (v1 == v0 && i1 < i0));
        int sel = second ? i1 : i0;
        si[tid] = sel;
        sl[tid] = (double)(second ? v1 : v0);   // winning dist = ||x-q||^2
        if (out_size >= QSIZE + 1 + N_)
            out[QSIZE + 1 + n0 + tid] = (float)sel;
    }
    __syncthreads();

    // ---- fused quantized-output write: 4 chunks of 64 dims ---------------
    // Stage E[si[row]] rows through the (now free) A-region smem; stride-65
    // padding -> conflict-free on both phases.
    float* sq = (float*)(smem + SMA);           // [128][65]
    const int tl = tid & 127, dgrp = tid >> 7;  // dgrp 0/1
    for (int d0 = 0; d0 < D_; d0 += 64) {
#pragma unroll
        for (int i = 0; i < 8; i++) {
            int idx2 = tid + i * 256;           // 0..2047
            int row = idx2 >> 4, c = idx2 & 15;
            float4 v = *(const float4*)(Eg + (size_t)si[row] * D_ + d0 + c * 4);
            float* dstp = sq + row * 65 + c * 4;
            dstp[0] = v.x; dstp[1] = v.y; dstp[2] = v.z; dstp[3] = v.w;
        }
        __syncthreads();
#pragma unroll
        for (int dd = 0; dd < 32; dd++) {
            int d = d0 + dgrp * 32 + dd;
            out[((size_t)b * D_ + d) * T_ + t0 + tl] = sq[tl * 65 + dgrp * 32 + dd];
        }
        __syncthreads();
    }

    // ---- loss: reduce 128 doubles -> atomicAdd into g_loss ---------------
    for (int off = 64; off > 0; off >>= 1) {
        if (tid < off) sl[tid] += sl[tid + off];
        __syncthreads();
    }
    if (tid == 0) atomicAdd(&g_loss, sl[0]);
}

// ---------------------------------------------------------------------------
// Kernel 3: loss scalar only (indices + quantized already written).
// loss = q_latent + 0.25 * e_latent = 1.25 * mean(||x - q||^2 per element)
// ---------------------------------------------------------------------------
__global__ void finalize_kernel(float* __restrict__ out, int out_size) {
    if (threadIdx.x == 0 && blockIdx.x == 0 && out_size > QSIZE) {
        out[QSIZE] = (float)(g_loss * 1.25 / (double)QSIZE);
    }
}

// ---------------------------------------------------------------------------
extern "C" void kernel_launch(void* const* d_in, const int* in_sizes, int n_in,
                              void* d_out, int out_size) {
    const float* X = (const float*)d_in[0];   // [B, D, T] f32
    const float* E = (const float*)d_in[1];   // [K, D]   f32
    float* out = (float*)d_out;

    cudaFuncSetAttribute(argmin_mma_kernel,
                         cudaFuncAttributeMaxDynamicSharedMemorySize, SMTOT);

    e2_kernel<<<K_, 256>>>(E);
    splitE_kernel<<<K_, 256>>>(E);
    x2_kernel<<<dim3(T_ / 256, B_), 256>>>(X);
    argmin_mma_kernel<<<N_ / 128, 256, SMTOT>>>(X, E, out, out_size);
    finalize_kernel<<<1, 32>>>(out, out_size);
}